// round 4
// baseline (speedup 1.0000x reference)
#include <cuda_runtime.h>

// Psi11t flow force: F = 2*t*c0 * ( s x (Fs*b + Fbs) )
//   Fs = nbr4(s), b = s.Fs, Fbs = nbr4(s*b). Periodic 512x512, B=32, S=3.
// Register-marching stencil: 128 threads own the full Y=512 ring (float4 each),
// march XCHUNK x-rows. y-boundary scalars exchanged via double-buffered smem.

#define MASK 511
#define XCHUNK 16
#define NTH 128

__device__ __forceinline__ float4 operator+(float4 a, float4 b) {
    return make_float4(a.x + b.x, a.y + b.y, a.z + b.z, a.w + b.w);
}
__device__ __forceinline__ float4 operator*(float4 a, float4 b) {
    return make_float4(a.x * b.x, a.y * b.y, a.z * b.z, a.w * b.w);
}
__device__ __forceinline__ float4 fma4(float4 a, float4 b, float4 c) {
    return make_float4(fmaf(a.x, b.x, c.x), fmaf(a.y, b.y, c.y),
                       fmaf(a.z, b.z, c.z), fmaf(a.w, b.w, c.w));
}
// a*b - c*d, elementwise
__device__ __forceinline__ float4 crossm(float4 a, float4 b, float4 c, float4 d) {
    return make_float4(fmaf(a.x, b.x, -(c.x * d.x)), fmaf(a.y, b.y, -(c.y * d.y)),
                       fmaf(a.z, b.z, -(c.z * d.z)), fmaf(a.w, b.w, -(c.w * d.w)));
}
// shift down (y-1): {lw, a.x, a.y, a.z}
__device__ __forceinline__ float4 ymv(float4 a, float lw) {
    return make_float4(lw, a.x, a.y, a.z);
}
// shift up (y+1): {a.y, a.z, a.w, rx}
__device__ __forceinline__ float4 ypv(float4 a, float rx) {
    return make_float4(a.y, a.z, a.w, rx);
}
__device__ __forceinline__ float4 scale4(float k, float4 a) {
    return make_float4(k * a.x, k * a.y, k * a.z, k * a.w);
}

__global__ __launch_bounds__(NTH, 4) void psi11t_kernel(
    const float* __restrict__ s,
    const float* __restrict__ tt,
    const float* __restrict__ c0,
    float* __restrict__ out)
{
    // boundary-exchange buffers: rows 0-2 = s comps, row 3 = b. Double buffered.
    __shared__ float wb[2][4][NTH];   // each thread's .w  (left value for t+1)
    __shared__ float xb[2][4][NTH];   // each thread's .x  (right value for t-1)

    const int bb = blockIdx.y;
    const int x0 = blockIdx.x * XCHUNK;
    const int t  = threadIdx.x;
    const int tm = (t - 1) & (NTH - 1);
    const int tp = (t + 1) & (NTH - 1);
    const long base = (long)bb * (3L << 18);
    const float* sb = s + base;
    const int yo = 4 * t;

    const float coeff = 2.0f * tt[0] * c0[0];

    float4 sP[3], sC[3], sN[3], sN2[3], sPF[3];
    float4 bP, bC, bN;
    float  sClw[3], sCrx[3], sNlw[3], sNrx[3];
    float  bClw, bCrx;

    // ---------------- Prologue: rows x0-2 .. x0+2 ----------------
    {
        float4 sA[3];
        #pragma unroll
        for (int c = 0; c < 3; ++c) {
            const float* cp = sb + ((long)c << 18) + yo;
            sA[c]  = *(const float4*)(cp + ((long)((x0 - 2) & MASK) << 9));
            sP[c]  = *(const float4*)(cp + ((long)((x0 - 1) & MASK) << 9));
            sC[c]  = *(const float4*)(cp + ((long)( x0      & MASK) << 9));
            sN[c]  = *(const float4*)(cp + ((long)((x0 + 1) & MASK) << 9));
            sN2[c] = *(const float4*)(cp + ((long)((x0 + 2) & MASK) << 9));
        }

        // sP bounds -> buf0
        #pragma unroll
        for (int c = 0; c < 3; ++c) { wb[0][c][t] = sP[c].w; xb[0][c][t] = sP[c].x; }
        __syncthreads();
        float plw[3], prx[3];
        #pragma unroll
        for (int c = 0; c < 3; ++c) { plw[c] = wb[0][c][tm]; prx[c] = xb[0][c][tp]; }

        // sC bounds -> buf1
        #pragma unroll
        for (int c = 0; c < 3; ++c) { wb[1][c][t] = sC[c].w; xb[1][c][t] = sC[c].x; }
        __syncthreads();
        #pragma unroll
        for (int c = 0; c < 3; ++c) { sClw[c] = wb[1][c][tm]; sCrx[c] = xb[1][c][tp]; }

        // bP = sP . (sA + sC + ym(sP) + yp(sP))
        bP = make_float4(0.f, 0.f, 0.f, 0.f);
        #pragma unroll
        for (int c = 0; c < 3; ++c)
            bP = fma4(sP[c], sA[c] + sC[c] + ymv(sP[c], plw[c]) + ypv(sP[c], prx[c]), bP);

        // bC = sC . (sP + sN + ym(sC) + yp(sC))
        bC = make_float4(0.f, 0.f, 0.f, 0.f);
        #pragma unroll
        for (int c = 0; c < 3; ++c)
            bC = fma4(sC[c], sP[c] + sN[c] + ymv(sC[c], sClw[c]) + ypv(sC[c], sCrx[c]), bC);

        // sN bounds + bC bounds -> buf0 (safe: buf0 readers done before last sync)
        #pragma unroll
        for (int c = 0; c < 3; ++c) { wb[0][c][t] = sN[c].w; xb[0][c][t] = sN[c].x; }
        wb[0][3][t] = bC.w; xb[0][3][t] = bC.x;
        __syncthreads();
        #pragma unroll
        for (int c = 0; c < 3; ++c) { sNlw[c] = wb[0][c][tm]; sNrx[c] = xb[0][c][tp]; }
        bClw = wb[0][3][tm]; bCrx = xb[0][3][tp];
    }

    // ---------------- Main loop: output rows x0 .. x0+XCHUNK-1 ----------------
    #pragma unroll 1
    for (int i = 0; i < XCHUNK; ++i) {
        const int x = x0 + i;
        const int p = (i & 1) ^ 1;   // prologue used buf0 last; iter0 -> buf1

        // prefetch row x+3 (for next iteration's sN2)
        #pragma unroll
        for (int c = 0; c < 3; ++c)
            sPF[c] = *(const float4*)(sb + ((long)c << 18)
                                      + ((long)((x + 3) & MASK) << 9) + yo);

        // publish sN2 bounds
        #pragma unroll
        for (int c = 0; c < 3; ++c) { wb[p][c][t] = sN2[c].w; xb[p][c][t] = sN2[c].x; }

        // bN = sN . (sC + sN2 + ym(sN) + yp(sN))
        bN = make_float4(0.f, 0.f, 0.f, 0.f);
        #pragma unroll
        for (int c = 0; c < 3; ++c)
            bN = fma4(sN[c], sC[c] + sN2[c] + ymv(sN[c], sNlw[c]) + ypv(sN[c], sNrx[c]), bN);

        wb[p][3][t] = bN.w; xb[p][3][t] = bN.x;
        __syncthreads();

        float nlw[3], nrx[3];
        #pragma unroll
        for (int c = 0; c < 3; ++c) { nlw[c] = wb[p][c][tm]; nrx[c] = xb[p][c][tp]; }
        const float bNlw = wb[p][3][tm], bNrx = xb[p][3][tp];

        // F at row x
        const float4 bym = ymv(bC, bClw);
        const float4 byp = ypv(bC, bCrx);
        float4 Fv[3];
        #pragma unroll
        for (int c = 0; c < 3; ++c) {
            const float4 ymc = ymv(sC[c], sClw[c]);
            const float4 ypc = ypv(sC[c], sCrx[c]);
            const float4 Fs  = sP[c] + sN[c] + ymc + ypc;
            const float4 Fbs = fma4(sP[c], bP,
                               fma4(sN[c], bN,
                               fma4(ymc, bym, ypc * byp)));
            Fv[c] = fma4(Fs, bC, Fbs);
        }

        const float4 F0 = crossm(sC[1], Fv[2], sC[2], Fv[1]);
        const float4 F1 = crossm(sC[2], Fv[0], sC[0], Fv[2]);
        const float4 F2 = crossm(sC[0], Fv[1], sC[1], Fv[0]);

        float* op = out + base + (((long)x) << 9) + yo;
        *(float4*)(op)              = scale4(coeff, F0);
        *(float4*)(op + (1L << 18)) = scale4(coeff, F1);
        *(float4*)(op + (2L << 18)) = scale4(coeff, F2);

        // rotate pipeline
        #pragma unroll
        for (int c = 0; c < 3; ++c) {
            sP[c] = sC[c]; sC[c] = sN[c]; sN[c] = sN2[c]; sN2[c] = sPF[c];
            sClw[c] = sNlw[c]; sCrx[c] = sNrx[c];
            sNlw[c] = nlw[c];  sNrx[c] = nrx[c];
        }
        bP = bC; bC = bN;
        bClw = bNlw; bCrx = bNrx;
    }
}

extern "C" void kernel_launch(void* const* d_in, const int* in_sizes, int n_in,
                              void* d_out, int out_size)
{
    const float* s  = (const float*)d_in[0];
    const float* t  = (const float*)d_in[1];
    const float* c0 = (const float*)d_in[2];
    float* out = (float*)d_out;

    dim3 grid(512 / XCHUNK, 32);   // 32 x-strips * 32 batches = 1024 blocks
    psi11t_kernel<<<grid, NTH>>>(s, t, c0, out);
}